// round 1
// baseline (speedup 1.0000x reference)
#include <cuda_runtime.h>
#include <math.h>

// Problem constants (fixed by the dataset)
#define T_TOK 4096   // B*S = 2*2048
#define D_DIM 1024
#define H_DIM 2816
#define E_NUM 8
#define CAP   4096   // worst-case tokens per expert

// GEMM tiling
#define TM 128
#define TN 64
#define KC 16

// ---------------- static device scratch (no allocations allowed) -------------
__device__ float g_Hh[(size_t)E_NUM * CAP * H_DIM];   // silu(gate)*up, per slot
__device__ float g_Y [(size_t)E_NUM * CAP * D_DIM];   // weighted expert outputs
__device__ int   g_tok[E_NUM * CAP];
__device__ float g_wgt[E_NUM * CAP];
__device__ int   g_cnt[E_NUM];
__device__ int   g_slot[T_TOK * 2];

// ---------------- reset counters (graph replays must be idempotent) ----------
__global__ void k_zero() {
    if (threadIdx.x < E_NUM) g_cnt[threadIdx.x] = 0;
}

// ---------------- gating: scores + top-2 + scatter ---------------------------
// one warp per token
__global__ void k_gate(const float* __restrict__ x, const float* __restrict__ Wg) {
    int t = blockIdx.x * (blockDim.x >> 5) + (threadIdx.x >> 5);
    int lane = threadIdx.x & 31;
    if (t >= T_TOK) return;

    const float4* xr = (const float4*)(x + (size_t)t * D_DIM);
    float acc[E_NUM];
#pragma unroll
    for (int e = 0; e < E_NUM; e++) acc[e] = 0.f;

    for (int i = lane; i < D_DIM / 4; i += 32) {
        float4 xv = xr[i];
#pragma unroll
        for (int e = 0; e < E_NUM; e++) {
            float4 wv = ((const float4*)(Wg + (size_t)e * D_DIM))[i];
            acc[e] += xv.x * wv.x + xv.y * wv.y + xv.z * wv.z + xv.w * wv.w;
        }
    }
#pragma unroll
    for (int e = 0; e < E_NUM; e++)
#pragma unroll
        for (int o = 16; o > 0; o >>= 1)
            acc[e] += __shfl_xor_sync(0xffffffffu, acc[e], o);

    if (lane == 0) {
        // top-2, ties -> lower index (matches jax.lax.top_k)
        int e0 = 0; float v0 = acc[0];
#pragma unroll
        for (int e = 1; e < E_NUM; e++) if (acc[e] > v0) { v0 = acc[e]; e0 = e; }
        int e1 = -1; float v1 = -INFINITY;
#pragma unroll
        for (int e = 0; e < E_NUM; e++)
            if (e != e0 && acc[e] > v1) { v1 = acc[e]; e1 = e; }

        int i0 = atomicAdd(&g_cnt[e0], 1);
        g_tok[e0 * CAP + i0] = t;
        g_wgt[e0 * CAP + i0] = v0;
        g_slot[t * 2 + 0]    = e0 * CAP + i0;

        int i1 = atomicAdd(&g_cnt[e1], 1);
        g_tok[e1 * CAP + i1] = t;
        g_wgt[e1 * CAP + i1] = v1;
        g_slot[t * 2 + 1]    = e1 * CAP + i1;
    }
}

// ---------------- FFN stage 1: Hh = silu(X W1^T) * (X W2^T) ------------------
// block: 128 tokens x 64 h, dual-B GEMM sharing the X tile. 256 threads.
__global__ __launch_bounds__(256, 2)
void k_ffn1(const float* __restrict__ x,
            const float* __restrict__ W1,
            const float* __restrict__ W2) {
    int e  = blockIdx.x >> 5;          // CAP/TM = 32 m-tiles per expert
    int m0 = (blockIdx.x & 31) * TM;
    int cnt = g_cnt[e];
    if (m0 >= cnt) return;
    int n0 = blockIdx.y * TN;

    __shared__ float Xs [KC][TM];
    __shared__ float B1s[KC][TN];
    __shared__ float B2s[KC][TN];

    int tid = threadIdx.x;
    int tx = tid & 15;          // 16 -> 4 cols each = 64
    int ty = tid >> 4;          // 16 -> 8 rows each = 128
    int lr = tid >> 2;          // 0..63 load row
    int lk = (tid & 3) << 2;    // 0,4,8,12 (k offset in chunk)

    int tokA = g_tok[e * CAP + (m0 + lr)];
    int tokB = g_tok[e * CAP + (m0 + lr + 64)];
    tokA = min(max(tokA, 0), T_TOK - 1);   // rows >= cnt carry stale values; clamp
    tokB = min(max(tokB, 0), T_TOK - 1);
    const float* xA  = x  + (size_t)tokA * D_DIM;
    const float* xB  = x  + (size_t)tokB * D_DIM;
    const float* w1p = W1 + ((size_t)e * H_DIM + n0 + lr) * D_DIM;
    const float* w2p = W2 + ((size_t)e * H_DIM + n0 + lr) * D_DIM;

    float accG[8][4], accU[8][4];
#pragma unroll
    for (int i = 0; i < 8; i++)
#pragma unroll
        for (int j = 0; j < 4; j++) { accG[i][j] = 0.f; accU[i][j] = 0.f; }

    for (int kc = 0; kc < D_DIM; kc += KC) {
        float4 va  = *(const float4*)(xA  + kc + lk);
        float4 vb  = *(const float4*)(xB  + kc + lk);
        float4 w1v = *(const float4*)(w1p + kc + lk);
        float4 w2v = *(const float4*)(w2p + kc + lk);
        __syncthreads();
        Xs [lk + 0][lr]      = va.x;  Xs [lk + 1][lr]      = va.y;
        Xs [lk + 2][lr]      = va.z;  Xs [lk + 3][lr]      = va.w;
        Xs [lk + 0][lr + 64] = vb.x;  Xs [lk + 1][lr + 64] = vb.y;
        Xs [lk + 2][lr + 64] = vb.z;  Xs [lk + 3][lr + 64] = vb.w;
        B1s[lk + 0][lr] = w1v.x; B1s[lk + 1][lr] = w1v.y;
        B1s[lk + 2][lr] = w1v.z; B1s[lk + 3][lr] = w1v.w;
        B2s[lk + 0][lr] = w2v.x; B2s[lk + 1][lr] = w2v.y;
        B2s[lk + 2][lr] = w2v.z; B2s[lk + 3][lr] = w2v.w;
        __syncthreads();

#pragma unroll
        for (int kk = 0; kk < KC; kk++) {
            float4 a0 = *(const float4*)&Xs [kk][ty * 8];
            float4 a1 = *(const float4*)&Xs [kk][ty * 8 + 4];
            float4 b1 = *(const float4*)&B1s[kk][tx * 4];
            float4 b2 = *(const float4*)&B2s[kk][tx * 4];
            float am[8] = {a0.x, a0.y, a0.z, a0.w, a1.x, a1.y, a1.z, a1.w};
            float c1[4] = {b1.x, b1.y, b1.z, b1.w};
            float c2[4] = {b2.x, b2.y, b2.z, b2.w};
#pragma unroll
            for (int i = 0; i < 8; i++)
#pragma unroll
                for (int j = 0; j < 4; j++) {
                    accG[i][j] += am[i] * c1[j];
                    accU[i][j] += am[i] * c2[j];
                }
        }
    }

#pragma unroll
    for (int i = 0; i < 8; i++) {
        int row = m0 + ty * 8 + i;
        if (row < cnt) {
            float4 o;
            float g, s;
            g = accG[i][0]; s = g / (1.f + __expf(-g)); o.x = s * accU[i][0];
            g = accG[i][1]; s = g / (1.f + __expf(-g)); o.y = s * accU[i][1];
            g = accG[i][2]; s = g / (1.f + __expf(-g)); o.z = s * accU[i][2];
            g = accG[i][3]; s = g / (1.f + __expf(-g)); o.w = s * accU[i][3];
            *(float4*)&g_Hh[((size_t)e * CAP + row) * H_DIM + n0 + tx * 4] = o;
        }
    }
}

// ---------------- FFN stage 2: Y = w * (Hh @ W3[e](D,H)^T) -------------------
__global__ __launch_bounds__(256, 2)
void k_ffn2(const float* __restrict__ W3) {
    int e  = blockIdx.x >> 5;
    int m0 = (blockIdx.x & 31) * TM;
    int cnt = g_cnt[e];
    if (m0 >= cnt) return;
    int n0 = blockIdx.y * TN;

    __shared__ float As[KC][TM];
    __shared__ float Bs[KC][TN];

    int tid = threadIdx.x;
    int tx = tid & 15;
    int ty = tid >> 4;
    int lr = tid >> 2;
    int lk = (tid & 3) << 2;

    const float* aA = g_Hh + ((size_t)e * CAP + m0 + lr) * H_DIM;
    const float* aB = g_Hh + ((size_t)e * CAP + m0 + lr + 64) * H_DIM;
    const float* bp = W3   + ((size_t)e * D_DIM + n0 + lr) * H_DIM;

    float acc[8][4];
#pragma unroll
    for (int i = 0; i < 8; i++)
#pragma unroll
        for (int j = 0; j < 4; j++) acc[i][j] = 0.f;

    for (int kc = 0; kc < H_DIM; kc += KC) {
        float4 va = *(const float4*)(aA + kc + lk);
        float4 vb = *(const float4*)(aB + kc + lk);
        float4 wv = *(const float4*)(bp + kc + lk);
        __syncthreads();
        As[lk + 0][lr]      = va.x;  As[lk + 1][lr]      = va.y;
        As[lk + 2][lr]      = va.z;  As[lk + 3][lr]      = va.w;
        As[lk + 0][lr + 64] = vb.x;  As[lk + 1][lr + 64] = vb.y;
        As[lk + 2][lr + 64] = vb.z;  As[lk + 3][lr + 64] = vb.w;
        Bs[lk + 0][lr] = wv.x; Bs[lk + 1][lr] = wv.y;
        Bs[lk + 2][lr] = wv.z; Bs[lk + 3][lr] = wv.w;
        __syncthreads();

#pragma unroll
        for (int kk = 0; kk < KC; kk++) {
            float4 a0 = *(const float4*)&As[kk][ty * 8];
            float4 a1 = *(const float4*)&As[kk][ty * 8 + 4];
            float4 b0 = *(const float4*)&Bs[kk][tx * 4];
            float am[8] = {a0.x, a0.y, a0.z, a0.w, a1.x, a1.y, a1.z, a1.w};
            float bn[4] = {b0.x, b0.y, b0.z, b0.w};
#pragma unroll
            for (int i = 0; i < 8; i++)
#pragma unroll
                for (int j = 0; j < 4; j++)
                    acc[i][j] += am[i] * bn[j];
        }
    }

#pragma unroll
    for (int i = 0; i < 8; i++) {
        int row = m0 + ty * 8 + i;
        if (row < cnt) {
            float w = g_wgt[e * CAP + row];
            float4 o;
            o.x = acc[i][0] * w; o.y = acc[i][1] * w;
            o.z = acc[i][2] * w; o.w = acc[i][3] * w;
            *(float4*)&g_Y[((size_t)e * CAP + row) * D_DIM + n0 + tx * 4] = o;
        }
    }
}

// ---------------- combine: out[t] = Y[slot0] + Y[slot1] ----------------------
__global__ void k_combine(float* __restrict__ out) {
    int idx = blockIdx.x * 256 + threadIdx.x;       // over T*D/4
    int t = idx >> 8;                               // D/4 = 256 vec4 per token
    int c = idx & 255;
    int s0 = g_slot[t * 2 + 0];
    int s1 = g_slot[t * 2 + 1];
    const float4* Y4 = (const float4*)g_Y;
    float4 a = Y4[(size_t)s0 * (D_DIM / 4) + c];
    float4 b = Y4[(size_t)s1 * (D_DIM / 4) + c];
    float4 o; o.x = a.x + b.x; o.y = a.y + b.y; o.z = a.z + b.z; o.w = a.w + b.w;
    ((float4*)out)[idx] = o;
}

// -----------------------------------------------------------------------------
extern "C" void kernel_launch(void* const* d_in, const int* in_sizes, int n_in,
                              void* d_out, int out_size) {
    const float* x  = (const float*)d_in[0];
    const float* Wg = (const float*)d_in[1];
    const float* W1 = (const float*)d_in[2];
    const float* W2 = (const float*)d_in[3];
    const float* W3 = (const float*)d_in[4];
    float* out = (float*)d_out;

    k_zero<<<1, 32>>>();
    k_gate<<<T_TOK / 8, 256>>>(x, Wg);

    dim3 g1(E_NUM * (CAP / TM), H_DIM / TN);   // (256, 44)
    k_ffn1<<<g1, 256>>>(x, W1, W2);

    dim3 g2(E_NUM * (CAP / TM), D_DIM / TN);   // (256, 16)
    k_ffn2<<<g2, 256>>>(W3);

    k_combine<<<(T_TOK * D_DIM / 4) / 256, 256>>>(out);
}

// round 3
// speedup vs baseline: 2.5624x; 2.5624x over previous
#include <cuda_runtime.h>
#include <cstdint>
#include <math.h>

// ---------------- problem constants ------------------------------------------
#define T_TOK 4096
#define D_DIM 1024
#define H_DIM 2816
#define E_NUM 8
#define CAP   4096

#define BM 128
#define BN 128
#define BK 16
#define RS 20                      // padded smem row stride (floats): conflict-free
#define ATILE_F (BM * RS)          // 2560 floats = 10240 B per tile
#define NK1 (D_DIM / BK)           // 64
#define NK2 (H_DIM / BK)           // 176

#define SMEM1_BYTES (3 * 3 * ATILE_F * 4)   // 3 stages x (A,B1,B2) = 92160
#define SMEM2_BYTES (4 * 2 * ATILE_F * 4)   // 4 stages x (A,B)     = 81920

// ---------------- static device scratch --------------------------------------
__device__ float g_xc [(size_t)T_TOK * D_DIM];
__device__ float g_W1c[(size_t)E_NUM * H_DIM * D_DIM];
__device__ float g_W2c[(size_t)E_NUM * H_DIM * D_DIM];
__device__ float g_W3c[(size_t)E_NUM * D_DIM * H_DIM];
__device__ float g_Hh [(size_t)E_NUM * CAP * H_DIM];
__device__ float g_Y  [(size_t)E_NUM * CAP * D_DIM];
__device__ int   g_tok[E_NUM * CAP];
__device__ float g_wgt[E_NUM * CAP];
__device__ int   g_cnt[E_NUM];
__device__ int   g_slot[T_TOK * 2];

// ---------------- helpers -----------------------------------------------------
__device__ __forceinline__ uint32_t s2u(const void* p) {
    uint32_t a;
    asm("{ .reg .u64 t; cvta.to.shared.u64 t, %1; cvt.u32.u64 %0, t; }" : "=r"(a) : "l"(p));
    return a;
}

#define CPA16(s, g) asm volatile("cp.async.cg.shared.global [%0], [%1], 16;" :: "r"(s), "l"(g))
#define CPA_COMMIT() asm volatile("cp.async.commit_group;" ::: "memory")
#define CPA_WAIT(n)  asm volatile("cp.async.wait_group %0;" :: "n"(n) : "memory")

// m16n8k8 tf32 MMA, fp32 accum
#define MMA_TF32(d, a, b)                                                         \
    asm volatile(                                                                 \
        "mma.sync.aligned.m16n8k8.row.col.f32.tf32.tf32.f32 "                     \
        "{%0,%1,%2,%3},{%4,%5,%6,%7},{%8,%9},{%0,%1,%2,%3};"                      \
        : "+f"((d)[0]), "+f"((d)[1]), "+f"((d)[2]), "+f"((d)[3])                  \
        : "r"((a)[0]), "r"((a)[1]), "r"((a)[2]), "r"((a)[3]),                     \
          "r"((b)[0]), "r"((b)[1]))

// RN-even round fp32 -> tf32 bit pattern
__device__ __forceinline__ uint32_t tf32r(uint32_t u) {
    uint32_t l = (u >> 13) & 1u;
    return (u + 0xFFFu + l) & 0xFFFFE000u;
}

// ---------------- pre-rounding pass ------------------------------------------
__global__ void k_round4(const float4* __restrict__ s, float4* __restrict__ d, int n4) {
    int i = blockIdx.x * 256 + threadIdx.x;
    if (i >= n4) return;
    float4 v = s[i];
    float4 o;
    o.x = __uint_as_float(tf32r(__float_as_uint(v.x)));
    o.y = __uint_as_float(tf32r(__float_as_uint(v.y)));
    o.z = __uint_as_float(tf32r(__float_as_uint(v.z)));
    o.w = __uint_as_float(tf32r(__float_as_uint(v.w)));
    d[i] = o;
}

// ---------------- counters / gating / combine --------------------------------
__global__ void k_zero() {
    if (threadIdx.x < E_NUM) g_cnt[threadIdx.x] = 0;
}

__global__ void k_gate(const float* __restrict__ x, const float* __restrict__ Wg) {
    int t = blockIdx.x * (blockDim.x >> 5) + (threadIdx.x >> 5);
    int lane = threadIdx.x & 31;
    if (t >= T_TOK) return;
    const float4* xr = (const float4*)(x + (size_t)t * D_DIM);
    float acc[E_NUM];
#pragma unroll
    for (int e = 0; e < E_NUM; e++) acc[e] = 0.f;
    for (int i = lane; i < D_DIM / 4; i += 32) {
        float4 xv = xr[i];
#pragma unroll
        for (int e = 0; e < E_NUM; e++) {
            float4 wv = ((const float4*)(Wg + (size_t)e * D_DIM))[i];
            acc[e] += xv.x * wv.x + xv.y * wv.y + xv.z * wv.z + xv.w * wv.w;
        }
    }
#pragma unroll
    for (int e = 0; e < E_NUM; e++)
#pragma unroll
        for (int o = 16; o > 0; o >>= 1)
            acc[e] += __shfl_xor_sync(0xffffffffu, acc[e], o);
    if (lane == 0) {
        int e0 = 0; float v0 = acc[0];
#pragma unroll
        for (int e = 1; e < E_NUM; e++) if (acc[e] > v0) { v0 = acc[e]; e0 = e; }
        int e1 = -1; float v1 = -INFINITY;
#pragma unroll
        for (int e = 0; e < E_NUM; e++)
            if (e != e0 && acc[e] > v1) { v1 = acc[e]; e1 = e; }
        int i0 = atomicAdd(&g_cnt[e0], 1);
        g_tok[e0 * CAP + i0] = t; g_wgt[e0 * CAP + i0] = v0;
        g_slot[t * 2 + 0] = e0 * CAP + i0;
        int i1 = atomicAdd(&g_cnt[e1], 1);
        g_tok[e1 * CAP + i1] = t; g_wgt[e1 * CAP + i1] = v1;
        g_slot[t * 2 + 1] = e1 * CAP + i1;
    }
}

__global__ void k_combine(float* __restrict__ out) {
    int idx = blockIdx.x * 256 + threadIdx.x;
    int t = idx >> 8;
    int c = idx & 255;
    int s0 = g_slot[t * 2 + 0];
    int s1 = g_slot[t * 2 + 1];
    const float4* Y4 = (const float4*)g_Y;
    float4 a = Y4[(size_t)s0 * (D_DIM / 4) + c];
    float4 b = Y4[(size_t)s1 * (D_DIM / 4) + c];
    float4 o; o.x = a.x + b.x; o.y = a.y + b.y; o.z = a.z + b.z; o.w = a.w + b.w;
    ((float4*)out)[idx] = o;
}

// ---------------- GEMM1: Hh = silu(X W1^T) * (X W2^T) ------------------------
__global__ __launch_bounds__(256, 1)
void k_ffn1() {
    int e  = blockIdx.x >> 5;
    int m0 = (blockIdx.x & 31) * BM;
    int cnt = g_cnt[e];
    if (m0 >= cnt) return;
    int n0 = blockIdx.y * BN;

    extern __shared__ float sm[];
    const int STG = 3 * ATILE_F;               // floats per stage

    int tid  = threadIdx.x;
    int wid  = tid >> 5, lane = tid & 31;
    int wm0  = (wid & 1) * 64;
    int wn0  = (wid >> 1) * 32;
    int grp  = lane >> 2, tg = lane & 3;

    // loader geometry: thread -> (row = tid/2, col base = (tid&1)*8)
    int lrow = tid >> 1;
    int lc   = (tid & 1) * 8;
    int tok  = g_tok[e * CAP + m0 + lrow];
    tok = min(max(tok, 0), T_TOK - 1);
    const float* aS  = g_xc  + (size_t)tok * D_DIM + lc;
    const float* b1S = g_W1c + ((size_t)e * H_DIM + n0 + lrow) * D_DIM + lc;
    const float* b2S = g_W2c + ((size_t)e * H_DIM + n0 + lrow) * D_DIM + lc;
    uint32_t dst = s2u(sm) + (uint32_t)(lrow * RS + lc) * 4u;

#define LOAD1(k, stg) do {                                                      \
        int kc = (k) * BK;                                                      \
        uint32_t d0 = dst + (uint32_t)(stg) * STG * 4u;                         \
        CPA16(d0,                  aS  + kc); CPA16(d0 + 16,                  aS  + kc + 4); \
        CPA16(d0 + ATILE_F * 4,    b1S + kc); CPA16(d0 + ATILE_F * 4 + 16,    b1S + kc + 4); \
        CPA16(d0 + 2 * ATILE_F * 4, b2S + kc); CPA16(d0 + 2 * ATILE_F * 4 + 16, b2S + kc + 4); \
    } while (0)

    float accG[4][4][4], accU[4][4][4];
#pragma unroll
    for (int i = 0; i < 4; i++)
#pragma unroll
        for (int j = 0; j < 4; j++)
#pragma unroll
            for (int r = 0; r < 4; r++) { accG[i][j][r] = 0.f; accU[i][j][r] = 0.f; }

    LOAD1(0, 0); CPA_COMMIT();
    LOAD1(1, 1); CPA_COMMIT();

    int cs = 0;   // compute stage
    int ls = 2;   // load stage
    for (int k = 0; k < NK1; k++) {
        CPA_WAIT(1);
        __syncthreads();
        if (k + 2 < NK1) LOAD1(k + 2, ls);
        CPA_COMMIT();                            // empty group keeps counts exact
        if (++ls == 3) ls = 0;

        const uint32_t* As  = (const uint32_t*)(sm + cs * STG);
        const uint32_t* B1s = As + ATILE_F;
        const uint32_t* B2s = As + 2 * ATILE_F;
#pragma unroll
        for (int ks = 0; ks < 2; ks++) {
            uint32_t a[4][4];
#pragma unroll
            for (int mt = 0; mt < 4; mt++) {
                int r = wm0 + mt * 16 + grp;
                int c = ks * 8 + tg;
                a[mt][0] = As[r * RS + c];
                a[mt][1] = As[(r + 8) * RS + c];
                a[mt][2] = As[r * RS + c + 4];
                a[mt][3] = As[(r + 8) * RS + c + 4];
            }
            uint32_t b1[4][2], b2[4][2];
#pragma unroll
            for (int nt = 0; nt < 4; nt++) {
                int n = wn0 + nt * 8 + grp;
                int c = ks * 8 + tg;
                b1[nt][0] = B1s[n * RS + c];
                b1[nt][1] = B1s[n * RS + c + 4];
                b2[nt][0] = B2s[n * RS + c];
                b2[nt][1] = B2s[n * RS + c + 4];
            }
#pragma unroll
            for (int mt = 0; mt < 4; mt++)
#pragma unroll
                for (int nt = 0; nt < 4; nt++) {
                    MMA_TF32(accG[mt][nt], a[mt], b1[nt]);
                    MMA_TF32(accU[mt][nt], a[mt], b2[nt]);
                }
        }
        if (++cs == 3) cs = 0;
        __syncthreads();
    }
#undef LOAD1

    // epilogue: h = tf32(silu(g) * u)
#pragma unroll
    for (int mt = 0; mt < 4; mt++) {
#pragma unroll
        for (int nt = 0; nt < 4; nt++) {
            int r0 = m0 + wm0 + mt * 16 + grp;
            int cc = n0 + wn0 + nt * 8 + 2 * tg;
#pragma unroll
            for (int h = 0; h < 2; h++) {
                int row = r0 + h * 8;
                if (row < cnt) {
                    float gv0 = accG[mt][nt][2 * h + 0], uv0 = accU[mt][nt][2 * h + 0];
                    float gv1 = accG[mt][nt][2 * h + 1], uv1 = accU[mt][nt][2 * h + 1];
                    float h0 = (gv0 / (1.f + __expf(-gv0))) * uv0;
                    float h1 = (gv1 / (1.f + __expf(-gv1))) * uv1;
                    float2 o;
                    o.x = __uint_as_float(tf32r(__float_as_uint(h0)));
                    o.y = __uint_as_float(tf32r(__float_as_uint(h1)));
                    *(float2*)&g_Hh[((size_t)e * CAP + row) * H_DIM + cc] = o;
                }
            }
        }
    }
}

// ---------------- GEMM2: Y = wgt * (Hh @ W3[e]^T) ----------------------------
__global__ __launch_bounds__(256, 2)
void k_ffn2() {
    int e  = blockIdx.x >> 5;
    int m0 = (blockIdx.x & 31) * BM;
    int cnt = g_cnt[e];
    if (m0 >= cnt) return;
    int n0 = blockIdx.y * BN;

    extern __shared__ float sm[];
    const int STG = 2 * ATILE_F;

    int tid  = threadIdx.x;
    int wid  = tid >> 5, lane = tid & 31;
    int wm0  = (wid & 1) * 64;
    int wn0  = (wid >> 1) * 32;
    int grp  = lane >> 2, tg = lane & 3;

    int lrow = tid >> 1;
    int lc   = (tid & 1) * 8;
    const float* aS = g_Hh  + ((size_t)e * CAP + m0 + lrow) * H_DIM + lc;
    const float* bS = g_W3c + ((size_t)e * D_DIM + n0 + lrow) * H_DIM + lc;
    uint32_t dst = s2u(sm) + (uint32_t)(lrow * RS + lc) * 4u;

#define LOAD2(k, stg) do {                                                      \
        int kc = (k) * BK;                                                      \
        uint32_t d0 = dst + (uint32_t)(stg) * STG * 4u;                         \
        CPA16(d0,               aS + kc); CPA16(d0 + 16,               aS + kc + 4); \
        CPA16(d0 + ATILE_F * 4, bS + kc); CPA16(d0 + ATILE_F * 4 + 16, bS + kc + 4); \
    } while (0)

    float acc[4][4][4];
#pragma unroll
    for (int i = 0; i < 4; i++)
#pragma unroll
        for (int j = 0; j < 4; j++)
#pragma unroll
            for (int r = 0; r < 4; r++) acc[i][j][r] = 0.f;

    LOAD2(0, 0); CPA_COMMIT();
    LOAD2(1, 1); CPA_COMMIT();
    LOAD2(2, 2); CPA_COMMIT();

    int cs = 0;
    int ls = 3;
    for (int k = 0; k < NK2; k++) {
        CPA_WAIT(2);
        __syncthreads();
        if (k + 3 < NK2) LOAD2(k + 3, ls);
        CPA_COMMIT();
        if (++ls == 4) ls = 0;

        const uint32_t* As = (const uint32_t*)(sm + cs * STG);
        const uint32_t* Bs = As + ATILE_F;
#pragma unroll
        for (int ks = 0; ks < 2; ks++) {
            uint32_t a[4][4];
#pragma unroll
            for (int mt = 0; mt < 4; mt++) {
                int r = wm0 + mt * 16 + grp;
                int c = ks * 8 + tg;
                a[mt][0] = As[r * RS + c];
                a[mt][1] = As[(r + 8) * RS + c];
                a[mt][2] = As[r * RS + c + 4];
                a[mt][3] = As[(r + 8) * RS + c + 4];
            }
            uint32_t b[4][2];
#pragma unroll
            for (int nt = 0; nt < 4; nt++) {
                int n = wn0 + nt * 8 + grp;
                int c = ks * 8 + tg;
                b[nt][0] = Bs[n * RS + c];
                b[nt][1] = Bs[n * RS + c + 4];
            }
#pragma unroll
            for (int mt = 0; mt < 4; mt++)
#pragma unroll
                for (int nt = 0; nt < 4; nt++)
                    MMA_TF32(acc[mt][nt], a[mt], b[nt]);
        }
        if (++cs == 4) cs = 0;
        __syncthreads();
    }
#undef LOAD2

#pragma unroll
    for (int mt = 0; mt < 4; mt++) {
        int r0 = m0 + wm0 + mt * 16 + grp;
#pragma unroll
        for (int h = 0; h < 2; h++) {
            int row = r0 + h * 8;
            if (row < cnt) {
                float w = g_wgt[e * CAP + row];
#pragma unroll
                for (int nt = 0; nt < 4; nt++) {
                    int cc = n0 + wn0 + nt * 8 + 2 * tg;
                    float2 o;
                    o.x = acc[mt][nt][2 * h + 0] * w;
                    o.y = acc[mt][nt][2 * h + 1] * w;
                    *(float2*)&g_Y[((size_t)e * CAP + row) * D_DIM + cc] = o;
                }
            }
        }
    }
}

// -----------------------------------------------------------------------------
extern "C" void kernel_launch(void* const* d_in, const int* in_sizes, int n_in,
                              void* d_out, int out_size) {
    const float* x  = (const float*)d_in[0];
    const float* Wg = (const float*)d_in[1];
    const float* W1 = (const float*)d_in[2];
    const float* W2 = (const float*)d_in[3];
    const float* W3 = (const float*)d_in[4];
    float* out = (float*)d_out;

    cudaFuncSetAttribute(k_ffn1, cudaFuncAttributeMaxDynamicSharedMemorySize, SMEM1_BYTES);
    cudaFuncSetAttribute(k_ffn2, cudaFuncAttributeMaxDynamicSharedMemorySize, SMEM2_BYTES);

    void *p_xc, *p_w1, *p_w2, *p_w3;
    cudaGetSymbolAddress(&p_xc, g_xc);
    cudaGetSymbolAddress(&p_w1, g_W1c);
    cudaGetSymbolAddress(&p_w2, g_W2c);
    cudaGetSymbolAddress(&p_w3, g_W3c);

    k_zero<<<1, 32>>>();
    k_gate<<<T_TOK / 8, 256>>>(x, Wg);

    int n4x = T_TOK * D_DIM / 4;
    int n4w = E_NUM * H_DIM * D_DIM / 4;
    k_round4<<<(n4x + 255) / 256, 256>>>((const float4*)x,  (float4*)p_xc, n4x);
    k_round4<<<(n4w + 255) / 256, 256>>>((const float4*)W1, (float4*)p_w1, n4w);
    k_round4<<<(n4w + 255) / 256, 256>>>((const float4*)W2, (float4*)p_w2, n4w);
    k_round4<<<(n4w + 255) / 256, 256>>>((const float4*)W3, (float4*)p_w3, n4w);

    dim3 g1(E_NUM * (CAP / BM), H_DIM / BN);   // (256, 22)
    k_ffn1<<<g1, 256, SMEM1_BYTES>>>();

    dim3 g2(E_NUM * (CAP / BM), D_DIM / BN);   // (256, 8)
    k_ffn2<<<g2, 256, SMEM2_BYTES>>>();

    k_combine<<<(T_TOK * D_DIM / 4) / 256, 256>>>(out);
}

// round 6
// speedup vs baseline: 2.9902x; 1.1670x over previous
#include <cuda_runtime.h>
#include <cstdint>
#include <math.h>

// ---------------- problem constants ------------------------------------------
#define T_TOK 4096
#define D_DIM 1024
#define H_DIM 2816
#define E_NUM 8
#define CAP   4096

#define BM 128
#define BN 128
#define BK 16
#define RS 20                      // padded smem row stride (floats): conflict-free
#define ATILE_F (BM * RS)          // 2560 floats = 10240 B per tile
#define NK1 (D_DIM / BK)           // 64
#define NK2 (H_DIM / BK)           // 176

#define SMEM1_BYTES (3 * 3 * ATILE_F * 4)   // 3 stages x (A,B1,B2) = 92160
#define SMEM2_BYTES (4 * 2 * ATILE_F * 4)   // 4 stages x (A,B)     = 81920

// ---------------- static device scratch --------------------------------------
__device__ float g_xc [(size_t)T_TOK * D_DIM];
__device__ float g_W1c[(size_t)E_NUM * H_DIM * D_DIM];
__device__ float g_W2c[(size_t)E_NUM * H_DIM * D_DIM];
__device__ float g_W3c[(size_t)E_NUM * D_DIM * H_DIM];
__device__ float g_Hh [(size_t)E_NUM * CAP * H_DIM];
__device__ float g_Y  [(size_t)E_NUM * CAP * D_DIM];
__device__ int   g_tok[E_NUM * CAP];
__device__ float g_wgt[E_NUM * CAP];
__device__ int   g_cnt[E_NUM];
__device__ int   g_slot[T_TOK * 2];

// ---------------- helpers -----------------------------------------------------
__device__ __forceinline__ uint32_t s2u(const void* p) {
    uint32_t a;
    asm("{ .reg .u64 t; cvta.to.shared.u64 t, %1; cvt.u32.u64 %0, t; }" : "=r"(a) : "l"(p));
    return a;
}

#define CPA16(s, g) asm volatile("cp.async.cg.shared.global [%0], [%1], 16;" :: "r"(s), "l"(g))
#define CPA_COMMIT() asm volatile("cp.async.commit_group;" ::: "memory")
#define CPA_WAIT(n)  asm volatile("cp.async.wait_group %0;" :: "n"(n) : "memory")

// ldmatrix x4: four 8x8-b32 quadrants (as 8x16 b16 tiles); reg i = tile i,
// element [lane/4][lane%4] -- exactly the tf32 m16n8k8 fragment layout.
#define LDSM_X4(r, addr)                                                          \
    asm volatile("ldmatrix.sync.aligned.m8n8.x4.shared.b16 {%0,%1,%2,%3}, [%4];"  \
        : "=r"((r)[0]), "=r"((r)[1]), "=r"((r)[2]), "=r"((r)[3]) : "r"(addr))

// m16n8k8 tf32 MMA, fp32 accum
#define MMA_TF32(d, a, b)                                                         \
    asm volatile(                                                                 \
        "mma.sync.aligned.m16n8k8.row.col.f32.tf32.tf32.f32 "                     \
        "{%0,%1,%2,%3},{%4,%5,%6,%7},{%8,%9},{%0,%1,%2,%3};"                      \
        : "+f"((d)[0]), "+f"((d)[1]), "+f"((d)[2]), "+f"((d)[3])                  \
        : "r"((a)[0]), "r"((a)[1]), "r"((a)[2]), "r"((a)[3]),                     \
          "r"((b)[0]), "r"((b)[1]))

// RN-even round fp32 -> tf32 bit pattern
__device__ __forceinline__ uint32_t tf32r(uint32_t u) {
    uint32_t l = (u >> 13) & 1u;
    return (u + 0xFFFu + l) & 0xFFFFE000u;
}

// ---------------- pre-rounding pass ------------------------------------------
__global__ void k_round4(const float4* __restrict__ s, float4* __restrict__ d, int n4) {
    int i = blockIdx.x * 256 + threadIdx.x;
    if (i >= n4) return;
    float4 v = s[i];
    float4 o;
    o.x = __uint_as_float(tf32r(__float_as_uint(v.x)));
    o.y = __uint_as_float(tf32r(__float_as_uint(v.y)));
    o.z = __uint_as_float(tf32r(__float_as_uint(v.z)));
    o.w = __uint_as_float(tf32r(__float_as_uint(v.w)));
    d[i] = o;
}

// ---------------- counters / gating / combine --------------------------------
__global__ void k_zero() {
    if (threadIdx.x < E_NUM) g_cnt[threadIdx.x] = 0;
}

__global__ void k_gate(const float* __restrict__ x, const float* __restrict__ Wg) {
    int t = blockIdx.x * (blockDim.x >> 5) + (threadIdx.x >> 5);
    int lane = threadIdx.x & 31;
    if (t >= T_TOK) return;
    const float4* xr = (const float4*)(x + (size_t)t * D_DIM);
    float acc[E_NUM];
#pragma unroll
    for (int e = 0; e < E_NUM; e++) acc[e] = 0.f;
    for (int i = lane; i < D_DIM / 4; i += 32) {
        float4 xv = xr[i];
#pragma unroll
        for (int e = 0; e < E_NUM; e++) {
            float4 wv = ((const float4*)(Wg + (size_t)e * D_DIM))[i];
            acc[e] += xv.x * wv.x + xv.y * wv.y + xv.z * wv.z + xv.w * wv.w;
        }
    }
#pragma unroll
    for (int e = 0; e < E_NUM; e++)
#pragma unroll
        for (int o = 16; o > 0; o >>= 1)
            acc[e] += __shfl_xor_sync(0xffffffffu, acc[e], o);
    if (lane == 0) {
        int e0 = 0; float v0 = acc[0];
#pragma unroll
        for (int e = 1; e < E_NUM; e++) if (acc[e] > v0) { v0 = acc[e]; e0 = e; }
        int e1 = -1; float v1 = -INFINITY;
#pragma unroll
        for (int e = 0; e < E_NUM; e++)
            if (e != e0 && acc[e] > v1) { v1 = acc[e]; e1 = e; }
        int i0 = atomicAdd(&g_cnt[e0], 1);
        g_tok[e0 * CAP + i0] = t; g_wgt[e0 * CAP + i0] = v0;
        g_slot[t * 2 + 0] = e0 * CAP + i0;
        int i1 = atomicAdd(&g_cnt[e1], 1);
        g_tok[e1 * CAP + i1] = t; g_wgt[e1 * CAP + i1] = v1;
        g_slot[t * 2 + 1] = e1 * CAP + i1;
    }
}

__global__ void k_combine(float* __restrict__ out) {
    int idx = blockIdx.x * 256 + threadIdx.x;
    int t = idx >> 8;
    int c = idx & 255;
    int s0 = g_slot[t * 2 + 0];
    int s1 = g_slot[t * 2 + 1];
    const float4* Y4 = (const float4*)g_Y;
    float4 a = Y4[(size_t)s0 * (D_DIM / 4) + c];
    float4 b = Y4[(size_t)s1 * (D_DIM / 4) + c];
    float4 o; o.x = a.x + b.x; o.y = a.y + b.y; o.z = a.z + b.z; o.w = a.w + b.w;
    ((float4*)out)[idx] = o;
}

// ---------------- GEMM1: Hh = silu(X W1^T) * (X W2^T) ------------------------
__global__ __launch_bounds__(256, 1)
void k_ffn1() {
    int e  = blockIdx.x >> 5;
    int m0 = (blockIdx.x & 31) * BM;
    int cnt = g_cnt[e];
    if (m0 >= cnt) return;
    int n0 = blockIdx.y * BN;

    extern __shared__ float sm[];
    const int STG = 3 * ATILE_F;               // floats per stage

    int tid  = threadIdx.x;
    int wid  = tid >> 5, lane = tid & 31;
    int wm0  = (wid & 1) * 64;
    int wn0  = (wid >> 1) * 32;
    int grp  = lane >> 2, tg = lane & 3;

    // ldmatrix lane geometry
    int lt = lane >> 3, lr = lane & 7;
    uint32_t smb = s2u(sm);
    // A: tile0 rows+0 c0-3, tile1 rows+8 c0-3, tile2 rows+0 c4-7, tile3 rows+8 c4-7
    uint32_t aAdr = smb + (uint32_t)((wm0 + (lt & 1) * 8 + lr) * RS + (lt >> 1) * 4) * 4u;
    // B: tile0 n+0 c0-3, tile1 n+0 c4-7, tile2 n+8 c0-3, tile3 n+8 c4-7
    uint32_t bAdr = smb + (uint32_t)((wn0 + (lt >> 1) * 8 + lr) * RS + (lt & 1) * 4) * 4u;

    // loader geometry: thread -> (row = tid/2, col base = (tid&1)*8)
    int lrow = tid >> 1;
    int lc   = (tid & 1) * 8;
    int tok  = g_tok[e * CAP + m0 + lrow];
    tok = min(max(tok, 0), T_TOK - 1);
    const float* aS  = g_xc  + (size_t)tok * D_DIM + lc;
    const float* b1S = g_W1c + ((size_t)e * H_DIM + n0 + lrow) * D_DIM + lc;
    const float* b2S = g_W2c + ((size_t)e * H_DIM + n0 + lrow) * D_DIM + lc;
    uint32_t dst = smb + (uint32_t)(lrow * RS + lc) * 4u;

#define LOAD1(k, stg) do {                                                      \
        int kc = (k) * BK;                                                      \
        uint32_t d0 = dst + (uint32_t)(stg) * STG * 4u;                         \
        CPA16(d0,                  aS  + kc); CPA16(d0 + 16,                  aS  + kc + 4); \
        CPA16(d0 + ATILE_F * 4,    b1S + kc); CPA16(d0 + ATILE_F * 4 + 16,    b1S + kc + 4); \
        CPA16(d0 + 2 * ATILE_F * 4, b2S + kc); CPA16(d0 + 2 * ATILE_F * 4 + 16, b2S + kc + 4); \
    } while (0)

    float accG[4][4][4], accU[4][4][4];
#pragma unroll
    for (int i = 0; i < 4; i++)
#pragma unroll
        for (int j = 0; j < 4; j++)
#pragma unroll
            for (int r = 0; r < 4; r++) { accG[i][j][r] = 0.f; accU[i][j][r] = 0.f; }

    LOAD1(0, 0); CPA_COMMIT();
    LOAD1(1, 1); CPA_COMMIT();

    int cs = 0;   // compute stage
    int ls = 2;   // load stage
    for (int k = 0; k < NK1; k++) {
        CPA_WAIT(1);
        __syncthreads();
        if (k + 2 < NK1) LOAD1(k + 2, ls);
        CPA_COMMIT();                            // one group per iter keeps counts exact
        if (++ls == 3) ls = 0;

        uint32_t sA  = aAdr + (uint32_t)(cs * STG) * 4u;
        uint32_t sB1 = bAdr + (uint32_t)(cs * STG + ATILE_F) * 4u;
        uint32_t sB2 = bAdr + (uint32_t)(cs * STG + 2 * ATILE_F) * 4u;
#pragma unroll
        for (int ks = 0; ks < 2; ks++) {
            uint32_t a[4][4];
#pragma unroll
            for (int mt = 0; mt < 4; mt++)
                LDSM_X4(a[mt], sA + (uint32_t)(mt * 16 * RS + ks * 8) * 4u);
            uint32_t b1[2][4], b2[2][4];
#pragma unroll
            for (int p = 0; p < 2; p++) {
                LDSM_X4(b1[p], sB1 + (uint32_t)(p * 16 * RS + ks * 8) * 4u);
                LDSM_X4(b2[p], sB2 + (uint32_t)(p * 16 * RS + ks * 8) * 4u);
            }
#pragma unroll
            for (int mt = 0; mt < 4; mt++)
#pragma unroll
                for (int nt = 0; nt < 4; nt++) {
                    MMA_TF32(accG[mt][nt], a[mt], &b1[nt >> 1][(nt & 1) * 2]);
                    MMA_TF32(accU[mt][nt], a[mt], &b2[nt >> 1][(nt & 1) * 2]);
                }
        }
        if (++cs == 3) cs = 0;
    }
#undef LOAD1

    // epilogue: h = tf32(silu(g) * u)
#pragma unroll
    for (int mt = 0; mt < 4; mt++) {
#pragma unroll
        for (int nt = 0; nt < 4; nt++) {
            int r0 = m0 + wm0 + mt * 16 + grp;
            int cc = n0 + wn0 + nt * 8 + 2 * tg;
#pragma unroll
            for (int h = 0; h < 2; h++) {
                int row = r0 + h * 8;
                if (row < cnt) {
                    float gv0 = accG[mt][nt][2 * h + 0], uv0 = accU[mt][nt][2 * h + 0];
                    float gv1 = accG[mt][nt][2 * h + 1], uv1 = accU[mt][nt][2 * h + 1];
                    float h0 = (gv0 / (1.f + __expf(-gv0))) * uv0;
                    float h1 = (gv1 / (1.f + __expf(-gv1))) * uv1;
                    float2 o;
                    o.x = __uint_as_float(tf32r(__float_as_uint(h0)));
                    o.y = __uint_as_float(tf32r(__float_as_uint(h1)));
                    *(float2*)&g_Hh[((size_t)e * CAP + row) * H_DIM + cc] = o;
                }
            }
        }
    }
}

// ---------------- GEMM2: Y = wgt * (Hh @ W3[e]^T) ----------------------------
__global__ __launch_bounds__(256, 2)
void k_ffn2() {
    int e  = blockIdx.x >> 5;
    int m0 = (blockIdx.x & 31) * BM;
    int cnt = g_cnt[e];
    if (m0 >= cnt) return;
    int n0 = blockIdx.y * BN;

    extern __shared__ float sm[];
    const int STG = 2 * ATILE_F;

    int tid  = threadIdx.x;
    int wid  = tid >> 5, lane = tid & 31;
    int wm0  = (wid & 1) * 64;
    int wn0  = (wid >> 1) * 32;
    int grp  = lane >> 2, tg = lane & 3;

    int lt = lane >> 3, lr = lane & 7;
    uint32_t smb = s2u(sm);
    uint32_t aAdr = smb + (uint32_t)((wm0 + (lt & 1) * 8 + lr) * RS + (lt >> 1) * 4) * 4u;
    uint32_t bAdr = smb + (uint32_t)((wn0 + (lt >> 1) * 8 + lr) * RS + (lt & 1) * 4) * 4u;

    int lrow = tid >> 1;
    int lc   = (tid & 1) * 8;
    const float* aS = g_Hh  + ((size_t)e * CAP + m0 + lrow) * H_DIM + lc;
    const float* bS = g_W3c + ((size_t)e * D_DIM + n0 + lrow) * H_DIM + lc;
    uint32_t dst = smb + (uint32_t)(lrow * RS + lc) * 4u;

#define LOAD2(k, stg) do {                                                      \
        int kc = (k) * BK;                                                      \
        uint32_t d0 = dst + (uint32_t)(stg) * STG * 4u;                         \
        CPA16(d0,               aS + kc); CPA16(d0 + 16,               aS + kc + 4); \
        CPA16(d0 + ATILE_F * 4, bS + kc); CPA16(d0 + ATILE_F * 4 + 16, bS + kc + 4); \
    } while (0)

    float acc[4][4][4];
#pragma unroll
    for (int i = 0; i < 4; i++)
#pragma unroll
        for (int j = 0; j < 4; j++)
#pragma unroll
            for (int r = 0; r < 4; r++) acc[i][j][r] = 0.f;

    LOAD2(0, 0); CPA_COMMIT();
    LOAD2(1, 1); CPA_COMMIT();
    LOAD2(2, 2); CPA_COMMIT();

    int cs = 0;
    int ls = 3;
    for (int k = 0; k < NK2; k++) {
        CPA_WAIT(2);
        __syncthreads();
        if (k + 3 < NK2) LOAD2(k + 3, ls);
        CPA_COMMIT();
        if (++ls == 4) ls = 0;

        uint32_t sA = aAdr + (uint32_t)(cs * STG) * 4u;
        uint32_t sB = bAdr + (uint32_t)(cs * STG + ATILE_F) * 4u;
#pragma unroll
        for (int ks = 0; ks < 2; ks++) {
            uint32_t a[4][4];
#pragma unroll
            for (int mt = 0; mt < 4; mt++)
                LDSM_X4(a[mt], sA + (uint32_t)(mt * 16 * RS + ks * 8) * 4u);
            uint32_t b[2][4];
#pragma unroll
            for (int p = 0; p < 2; p++)
                LDSM_X4(b[p], sB + (uint32_t)(p * 16 * RS + ks * 8) * 4u);
#pragma unroll
            for (int mt = 0; mt < 4; mt++)
#pragma unroll
                for (int nt = 0; nt < 4; nt++)
                    MMA_TF32(acc[mt][nt], a[mt], &b[nt >> 1][(nt & 1) * 2]);
        }
        if (++cs == 4) cs = 0;
    }
#undef LOAD2

#pragma unroll
    for (int mt = 0; mt < 4; mt++) {
        int r0 = m0 + wm0 + mt * 16 + grp;
#pragma unroll
        for (int h = 0; h < 2; h++) {
            int row = r0 + h * 8;
            if (row < cnt) {
                float w = g_wgt[e * CAP + row];
#pragma unroll
                for (int nt = 0; nt < 4; nt++) {
                    int cc = n0 + wn0 + nt * 8 + 2 * tg;
                    float2 o;
                    o.x = acc[mt][nt][2 * h + 0] * w;
                    o.y = acc[mt][nt][2 * h + 1] * w;
                    *(float2*)&g_Y[((size_t)e * CAP + row) * D_DIM + cc] = o;
                }
            }
        }
    }
}

// -----------------------------------------------------------------------------
extern "C" void kernel_launch(void* const* d_in, const int* in_sizes, int n_in,
                              void* d_out, int out_size) {
    const float* x  = (const float*)d_in[0];
    const float* Wg = (const float*)d_in[1];
    const float* W1 = (const float*)d_in[2];
    const float* W2 = (const float*)d_in[3];
    const float* W3 = (const float*)d_in[4];
    float* out = (float*)d_out;

    cudaFuncSetAttribute(k_ffn1, cudaFuncAttributeMaxDynamicSharedMemorySize, SMEM1_BYTES);
    cudaFuncSetAttribute(k_ffn2, cudaFuncAttributeMaxDynamicSharedMemorySize, SMEM2_BYTES);

    void *p_xc, *p_w1, *p_w2, *p_w3;
    cudaGetSymbolAddress(&p_xc, g_xc);
    cudaGetSymbolAddress(&p_w1, g_W1c);
    cudaGetSymbolAddress(&p_w2, g_W2c);
    cudaGetSymbolAddress(&p_w3, g_W3c);

    int n4x = T_TOK * D_DIM / 4;
    int n4w = E_NUM * H_DIM * D_DIM / 4;

    // Launch order chosen so ncu (-s 5 -c 1) profiles k_ffn1 (launch #6).
    k_zero<<<1, 32>>>();                                                     // 1
    k_gate<<<T_TOK / 8, 256>>>(x, Wg);                                       // 2
    k_round4<<<(n4x + 255) / 256, 256>>>((const float4*)x,  (float4*)p_xc, n4x);  // 3
    k_round4<<<(n4w + 255) / 256, 256>>>((const float4*)W1, (float4*)p_w1, n4w);  // 4
    k_round4<<<(n4w + 255) / 256, 256>>>((const float4*)W2, (float4*)p_w2, n4w);  // 5

    dim3 g1(E_NUM * (CAP / BM), H_DIM / BN);   // (256, 22)
    k_ffn1<<<g1, 256, SMEM1_BYTES>>>();                                      // 6 <- profiled

    k_round4<<<(n4w + 255) / 256, 256>>>((const float4*)W3, (float4*)p_w3, n4w);  // 7

    dim3 g2(E_NUM * (CAP / BM), D_DIM / BN);   // (256, 8)
    k_ffn2<<<g2, 256, SMEM2_BYTES>>>();                                      // 8

    k_combine<<<(T_TOK * D_DIM / 4) / 256, 256>>>(out);                      // 9
}

// round 7
// speedup vs baseline: 3.1230x; 1.0444x over previous
#include <cuda_runtime.h>
#include <cstdint>
#include <math.h>

// ---------------- problem constants ------------------------------------------
#define T_TOK 4096
#define D_DIM 1024
#define H_DIM 2816
#define E_NUM 8
#define CAP   4096

#define BM 128
#define BN 128
#define BK 16
#define RS 20                      // padded smem row stride (floats): conflict-free
#define ATILE_F (BM * RS)          // 2560 floats = 10240 B per tile
#define NK1 (D_DIM / BK)           // 64
#define NK2 (H_DIM / BK)           // 176
#define NSTG 5                     // pipeline ring depth (prefetch distance 3)

#define SMEM1_BYTES (NSTG * 3 * ATILE_F * 4)   // 5 stages x (A,B1,B2) = 153600
#define SMEM2_BYTES (NSTG * 2 * ATILE_F * 4)   // 5 stages x (A,B)     = 102400

#define N4X ((long)T_TOK * D_DIM / 4)          // 1048576
#define N4W ((long)E_NUM * H_DIM * D_DIM / 4)  // 5767168

// ---------------- static device scratch --------------------------------------
__device__ float g_xc [(size_t)T_TOK * D_DIM];
__device__ float g_W1c[(size_t)E_NUM * H_DIM * D_DIM];
__device__ float g_W2c[(size_t)E_NUM * H_DIM * D_DIM];
__device__ float g_W3c[(size_t)E_NUM * D_DIM * H_DIM];
__device__ float g_Hh [(size_t)E_NUM * CAP * H_DIM];
__device__ float g_Y  [(size_t)E_NUM * CAP * D_DIM];
__device__ int   g_tok[E_NUM * CAP];
__device__ float g_wgt[E_NUM * CAP];
__device__ int   g_cnt[E_NUM];
__device__ int   g_slot[T_TOK * 2];

// ---------------- helpers -----------------------------------------------------
__device__ __forceinline__ uint32_t s2u(const void* p) {
    uint32_t a;
    asm("{ .reg .u64 t; cvta.to.shared.u64 t, %1; cvt.u32.u64 %0, t; }" : "=r"(a) : "l"(p));
    return a;
}

#define CPA16(s, g) asm volatile("cp.async.cg.shared.global [%0], [%1], 16;" :: "r"(s), "l"(g))
#define CPA_COMMIT() asm volatile("cp.async.commit_group;" ::: "memory")
#define CPA_WAIT(n)  asm volatile("cp.async.wait_group %0;" :: "n"(n) : "memory")

// ldmatrix x4: four 8x8-b32 quadrants (as 8x16 b16 tiles); reg i = tile i,
// element [lane/4][lane%4] -- exactly the tf32 m16n8k8 fragment layout.
#define LDSM_X4(r, addr)                                                          \
    asm volatile("ldmatrix.sync.aligned.m8n8.x4.shared.b16 {%0,%1,%2,%3}, [%4];"  \
        : "=r"((r)[0]), "=r"((r)[1]), "=r"((r)[2]), "=r"((r)[3]) : "r"(addr))

// m16n8k8 tf32 MMA, fp32 accum
#define MMA_TF32(d, a, b)                                                         \
    asm volatile(                                                                 \
        "mma.sync.aligned.m16n8k8.row.col.f32.tf32.tf32.f32 "                     \
        "{%0,%1,%2,%3},{%4,%5,%6,%7},{%8,%9},{%0,%1,%2,%3};"                      \
        : "+f"((d)[0]), "+f"((d)[1]), "+f"((d)[2]), "+f"((d)[3])                  \
        : "r"((a)[0]), "r"((a)[1]), "r"((a)[2]), "r"((a)[3]),                     \
          "r"((b)[0]), "r"((b)[1]))

// RN-even round fp32 -> tf32 bit pattern
__device__ __forceinline__ uint32_t tf32r(uint32_t u) {
    uint32_t l = (u >> 13) & 1u;
    return (u + 0xFFFu + l) & 0xFFFFE000u;
}

// ---------------- fused pre-rounding pass (x, W1, W2, W3) --------------------
__global__ void k_round_all(const float4* __restrict__ x,
                            const float4* __restrict__ W1,
                            const float4* __restrict__ W2,
                            const float4* __restrict__ W3,
                            float4* __restrict__ xc,
                            float4* __restrict__ w1c,
                            float4* __restrict__ w2c,
                            float4* __restrict__ w3c) {
    long i = (long)blockIdx.x * 256 + threadIdx.x;
    const float4* s;
    float4* d;
    long off;
    if (i < N4X) { s = x; d = xc; off = i; }
    else {
        long w = i - N4X;
        if (w < N4W)               { s = W1; d = w1c; off = w; }
        else if (w < 2 * N4W)      { s = W2; d = w2c; off = w - N4W; }
        else                       { s = W3; d = w3c; off = w - 2 * N4W; }
    }
    float4 v = s[off];
    float4 o;
    o.x = __uint_as_float(tf32r(__float_as_uint(v.x)));
    o.y = __uint_as_float(tf32r(__float_as_uint(v.y)));
    o.z = __uint_as_float(tf32r(__float_as_uint(v.z)));
    o.w = __uint_as_float(tf32r(__float_as_uint(v.w)));
    d[off] = o;
}

// ---------------- counters / gating / combine --------------------------------
__global__ void k_zero() {
    if (threadIdx.x < E_NUM) g_cnt[threadIdx.x] = 0;
}

__global__ void k_gate(const float* __restrict__ x, const float* __restrict__ Wg) {
    int t = blockIdx.x * (blockDim.x >> 5) + (threadIdx.x >> 5);
    int lane = threadIdx.x & 31;
    if (t >= T_TOK) return;
    const float4* xr = (const float4*)(x + (size_t)t * D_DIM);
    float acc[E_NUM];
#pragma unroll
    for (int e = 0; e < E_NUM; e++) acc[e] = 0.f;
    for (int i = lane; i < D_DIM / 4; i += 32) {
        float4 xv = xr[i];
#pragma unroll
        for (int e = 0; e < E_NUM; e++) {
            float4 wv = ((const float4*)(Wg + (size_t)e * D_DIM))[i];
            acc[e] += xv.x * wv.x + xv.y * wv.y + xv.z * wv.z + xv.w * wv.w;
        }
    }
#pragma unroll
    for (int e = 0; e < E_NUM; e++)
#pragma unroll
        for (int o = 16; o > 0; o >>= 1)
            acc[e] += __shfl_xor_sync(0xffffffffu, acc[e], o);
    if (lane == 0) {
        int e0 = 0; float v0 = acc[0];
#pragma unroll
        for (int e = 1; e < E_NUM; e++) if (acc[e] > v0) { v0 = acc[e]; e0 = e; }
        int e1 = -1; float v1 = -INFINITY;
#pragma unroll
        for (int e = 0; e < E_NUM; e++)
            if (e != e0 && acc[e] > v1) { v1 = acc[e]; e1 = e; }
        int i0 = atomicAdd(&g_cnt[e0], 1);
        g_tok[e0 * CAP + i0] = t; g_wgt[e0 * CAP + i0] = v0;
        g_slot[t * 2 + 0] = e0 * CAP + i0;
        int i1 = atomicAdd(&g_cnt[e1], 1);
        g_tok[e1 * CAP + i1] = t; g_wgt[e1 * CAP + i1] = v1;
        g_slot[t * 2 + 1] = e1 * CAP + i1;
    }
}

__global__ void k_combine(float* __restrict__ out) {
    int idx = blockIdx.x * 256 + threadIdx.x;
    int t = idx >> 8;
    int c = idx & 255;
    int s0 = g_slot[t * 2 + 0];
    int s1 = g_slot[t * 2 + 1];
    const float4* Y4 = (const float4*)g_Y;
    float4 a = Y4[(size_t)s0 * (D_DIM / 4) + c];
    float4 b = Y4[(size_t)s1 * (D_DIM / 4) + c];
    float4 o; o.x = a.x + b.x; o.y = a.y + b.y; o.z = a.z + b.z; o.w = a.w + b.w;
    ((float4*)out)[idx] = o;
}

// ---------------- GEMM1: Hh = silu(X W1^T) * (X W2^T) ------------------------
// 5-stage cp.async ring, prefetch distance 3, one barrier per 2 k-iters.
__global__ __launch_bounds__(256, 1)
void k_ffn1() {
    int e  = blockIdx.x >> 5;
    int m0 = (blockIdx.x & 31) * BM;
    int cnt = g_cnt[e];
    if (m0 >= cnt) return;
    int n0 = blockIdx.y * BN;

    extern __shared__ float sm[];
    const int STG = 3 * ATILE_F;               // floats per stage

    int tid  = threadIdx.x;
    int wid  = tid >> 5, lane = tid & 31;
    int wm0  = (wid & 1) * 64;
    int wn0  = (wid >> 1) * 32;
    int grp  = lane >> 2, tg = lane & 3;

    // ldmatrix lane geometry
    int lt = lane >> 3, lr = lane & 7;
    uint32_t smb = s2u(sm);
    uint32_t aAdr = smb + (uint32_t)((wm0 + (lt & 1) * 8 + lr) * RS + (lt >> 1) * 4) * 4u;
    uint32_t bAdr = smb + (uint32_t)((wn0 + (lt >> 1) * 8 + lr) * RS + (lt & 1) * 4) * 4u;

    // loader geometry: thread -> (row = tid/2, col base = (tid&1)*8)
    int lrow = tid >> 1;
    int lc   = (tid & 1) * 8;
    int tok  = g_tok[e * CAP + m0 + lrow];
    tok = min(max(tok, 0), T_TOK - 1);
    const float* aS  = g_xc  + (size_t)tok * D_DIM + lc;
    const float* b1S = g_W1c + ((size_t)e * H_DIM + n0 + lrow) * D_DIM + lc;
    const float* b2S = g_W2c + ((size_t)e * H_DIM + n0 + lrow) * D_DIM + lc;
    uint32_t dst = smb + (uint32_t)(lrow * RS + lc) * 4u;

#define LOAD1(k, stg) do {                                                      \
        int kc = (k) * BK;                                                      \
        uint32_t d0 = dst + (uint32_t)(stg) * STG * 4u;                         \
        CPA16(d0,                  aS  + kc); CPA16(d0 + 16,                  aS  + kc + 4); \
        CPA16(d0 + ATILE_F * 4,    b1S + kc); CPA16(d0 + ATILE_F * 4 + 16,    b1S + kc + 4); \
        CPA16(d0 + 2 * ATILE_F * 4, b2S + kc); CPA16(d0 + 2 * ATILE_F * 4 + 16, b2S + kc + 4); \
    } while (0)

    float accG[4][4][4], accU[4][4][4];
#pragma unroll
    for (int i = 0; i < 4; i++)
#pragma unroll
        for (int j = 0; j < 4; j++)
#pragma unroll
            for (int r = 0; r < 4; r++) { accG[i][j][r] = 0.f; accU[i][j][r] = 0.f; }

#define COMPUTE1(cs) do {                                                       \
        uint32_t sA  = aAdr + (uint32_t)((cs) * STG) * 4u;                      \
        uint32_t sB1 = bAdr + (uint32_t)((cs) * STG + ATILE_F) * 4u;            \
        uint32_t sB2 = bAdr + (uint32_t)((cs) * STG + 2 * ATILE_F) * 4u;        \
        _Pragma("unroll")                                                       \
        for (int ks = 0; ks < 2; ks++) {                                        \
            uint32_t a[4][4];                                                   \
            _Pragma("unroll")                                                   \
            for (int mt = 0; mt < 4; mt++)                                      \
                LDSM_X4(a[mt], sA + (uint32_t)(mt * 16 * RS + ks * 8) * 4u);    \
            uint32_t b1[2][4], b2[2][4];                                        \
            _Pragma("unroll")                                                   \
            for (int p = 0; p < 2; p++) {                                       \
                LDSM_X4(b1[p], sB1 + (uint32_t)(p * 16 * RS + ks * 8) * 4u);    \
                LDSM_X4(b2[p], sB2 + (uint32_t)(p * 16 * RS + ks * 8) * 4u);    \
            }                                                                   \
            _Pragma("unroll")                                                   \
            for (int mt = 0; mt < 4; mt++)                                      \
                _Pragma("unroll")                                               \
                for (int nt = 0; nt < 4; nt++) {                                \
                    MMA_TF32(accG[mt][nt], a[mt], &b1[nt >> 1][(nt & 1) * 2]);  \
                    MMA_TF32(accU[mt][nt], a[mt], &b2[nt >> 1][(nt & 1) * 2]);  \
                }                                                               \
        }                                                                       \
    } while (0)

    LOAD1(0, 0); CPA_COMMIT();
    LOAD1(1, 1); CPA_COMMIT();
    LOAD1(2, 2); CPA_COMMIT();

    int cs = 0, ls = 3;
    for (int k = 0; k < NK1; k += 2) {
        CPA_WAIT(1);                 // groups <= k+2 done: stages <= k+1 complete
        __syncthreads();             // publish stages k, k+1; retire reads <= k-1
        if (k + 3 < NK1) LOAD1(k + 3, ls);
        CPA_COMMIT();
        if (++ls == NSTG) ls = 0;
        COMPUTE1(cs);                // stage k
        if (++cs == NSTG) cs = 0;
        if (k + 4 < NK1) LOAD1(k + 4, ls);
        CPA_COMMIT();
        if (++ls == NSTG) ls = 0;
        COMPUTE1(cs);                // stage k+1
        if (++cs == NSTG) cs = 0;
    }
#undef LOAD1
#undef COMPUTE1

    // epilogue: h = tf32(silu(g) * u)
#pragma unroll
    for (int mt = 0; mt < 4; mt++) {
#pragma unroll
        for (int nt = 0; nt < 4; nt++) {
            int r0 = m0 + wm0 + mt * 16 + grp;
            int cc = n0 + wn0 + nt * 8 + 2 * tg;
#pragma unroll
            for (int h = 0; h < 2; h++) {
                int row = r0 + h * 8;
                if (row < cnt) {
                    float gv0 = accG[mt][nt][2 * h + 0], uv0 = accU[mt][nt][2 * h + 0];
                    float gv1 = accG[mt][nt][2 * h + 1], uv1 = accU[mt][nt][2 * h + 1];
                    float h0 = (gv0 / (1.f + __expf(-gv0))) * uv0;
                    float h1 = (gv1 / (1.f + __expf(-gv1))) * uv1;
                    float2 o;
                    o.x = __uint_as_float(tf32r(__float_as_uint(h0)));
                    o.y = __uint_as_float(tf32r(__float_as_uint(h1)));
                    *(float2*)&g_Hh[((size_t)e * CAP + row) * H_DIM + cc] = o;
                }
            }
        }
    }
}

// ---------------- GEMM2: Y = wgt * (Hh @ W3[e]^T) ----------------------------
__global__ __launch_bounds__(256, 2)
void k_ffn2() {
    int e  = blockIdx.x >> 5;
    int m0 = (blockIdx.x & 31) * BM;
    int cnt = g_cnt[e];
    if (m0 >= cnt) return;
    int n0 = blockIdx.y * BN;

    extern __shared__ float sm[];
    const int STG = 2 * ATILE_F;

    int tid  = threadIdx.x;
    int wid  = tid >> 5, lane = tid & 31;
    int wm0  = (wid & 1) * 64;
    int wn0  = (wid >> 1) * 32;
    int grp  = lane >> 2, tg = lane & 3;

    int lt = lane >> 3, lr = lane & 7;
    uint32_t smb = s2u(sm);
    uint32_t aAdr = smb + (uint32_t)((wm0 + (lt & 1) * 8 + lr) * RS + (lt >> 1) * 4) * 4u;
    uint32_t bAdr = smb + (uint32_t)((wn0 + (lt >> 1) * 8 + lr) * RS + (lt & 1) * 4) * 4u;

    int lrow = tid >> 1;
    int lc   = (tid & 1) * 8;
    const float* aS = g_Hh  + ((size_t)e * CAP + m0 + lrow) * H_DIM + lc;
    const float* bS = g_W3c + ((size_t)e * D_DIM + n0 + lrow) * H_DIM + lc;
    uint32_t dst = smb + (uint32_t)(lrow * RS + lc) * 4u;

#define LOAD2(k, stg) do {                                                      \
        int kc = (k) * BK;                                                      \
        uint32_t d0 = dst + (uint32_t)(stg) * STG * 4u;                         \
        CPA16(d0,               aS + kc); CPA16(d0 + 16,               aS + kc + 4); \
        CPA16(d0 + ATILE_F * 4, bS + kc); CPA16(d0 + ATILE_F * 4 + 16, bS + kc + 4); \
    } while (0)

    float acc[4][4][4];
#pragma unroll
    for (int i = 0; i < 4; i++)
#pragma unroll
        for (int j = 0; j < 4; j++)
#pragma unroll
            for (int r = 0; r < 4; r++) acc[i][j][r] = 0.f;

#define COMPUTE2(cs) do {                                                       \
        uint32_t sA = aAdr + (uint32_t)((cs) * STG) * 4u;                       \
        uint32_t sB = bAdr + (uint32_t)((cs) * STG + ATILE_F) * 4u;             \
        _Pragma("unroll")                                                       \
        for (int ks = 0; ks < 2; ks++) {                                        \
            uint32_t a[4][4];                                                   \
            _Pragma("unroll")                                                   \
            for (int mt = 0; mt < 4; mt++)                                      \
                LDSM_X4(a[mt], sA + (uint32_t)(mt * 16 * RS + ks * 8) * 4u);    \
            uint32_t b[2][4];                                                   \
            _Pragma("unroll")                                                   \
            for (int p = 0; p < 2; p++)                                         \
                LDSM_X4(b[p], sB + (uint32_t)(p * 16 * RS + ks * 8) * 4u);      \
            _Pragma("unroll")                                                   \
            for (int mt = 0; mt < 4; mt++)                                      \
                _Pragma("unroll")                                               \
                for (int nt = 0; nt < 4; nt++)                                  \
                    MMA_TF32(acc[mt][nt], a[mt], &b[nt >> 1][(nt & 1) * 2]);    \
        }                                                                       \
    } while (0)

    LOAD2(0, 0); CPA_COMMIT();
    LOAD2(1, 1); CPA_COMMIT();
    LOAD2(2, 2); CPA_COMMIT();

    int cs = 0, ls = 3;
    for (int k = 0; k < NK2; k += 2) {
        CPA_WAIT(1);
        __syncthreads();
        if (k + 3 < NK2) LOAD2(k + 3, ls);
        CPA_COMMIT();
        if (++ls == NSTG) ls = 0;
        COMPUTE2(cs);
        if (++cs == NSTG) cs = 0;
        if (k + 4 < NK2) LOAD2(k + 4, ls);
        CPA_COMMIT();
        if (++ls == NSTG) ls = 0;
        COMPUTE2(cs);
        if (++cs == NSTG) cs = 0;
    }
#undef LOAD2
#undef COMPUTE2

#pragma unroll
    for (int mt = 0; mt < 4; mt++) {
        int r0 = m0 + wm0 + mt * 16 + grp;
#pragma unroll
        for (int h = 0; h < 2; h++) {
            int row = r0 + h * 8;
            if (row < cnt) {
                float w = g_wgt[e * CAP + row];
#pragma unroll
                for (int nt = 0; nt < 4; nt++) {
                    int cc = n0 + wn0 + nt * 8 + 2 * tg;
                    float2 o;
                    o.x = acc[mt][nt][2 * h + 0] * w;
                    o.y = acc[mt][nt][2 * h + 1] * w;
                    *(float2*)&g_Y[((size_t)e * CAP + row) * D_DIM + cc] = o;
                }
            }
        }
    }
}

// -----------------------------------------------------------------------------
extern "C" void kernel_launch(void* const* d_in, const int* in_sizes, int n_in,
                              void* d_out, int out_size) {
    const float* x  = (const float*)d_in[0];
    const float* Wg = (const float*)d_in[1];
    const float* W1 = (const float*)d_in[2];
    const float* W2 = (const float*)d_in[3];
    const float* W3 = (const float*)d_in[4];
    float* out = (float*)d_out;

    cudaFuncSetAttribute(k_ffn1, cudaFuncAttributeMaxDynamicSharedMemorySize, SMEM1_BYTES);
    cudaFuncSetAttribute(k_ffn2, cudaFuncAttributeMaxDynamicSharedMemorySize, SMEM2_BYTES);

    void *p_xc, *p_w1, *p_w2, *p_w3;
    cudaGetSymbolAddress(&p_xc, g_xc);
    cudaGetSymbolAddress(&p_w1, g_W1c);
    cudaGetSymbolAddress(&p_w2, g_W2c);
    cudaGetSymbolAddress(&p_w3, g_W3c);

    long n4_total = N4X + 3 * N4W;                     // 18350080
    int  nblk     = (int)((n4_total + 255) / 256);     // 71680

    // Launch order: GEMMs sit at app launches #4 and #5 (where ncu -s5-c1 lands).
    k_round_all<<<nblk, 256>>>((const float4*)x,  (const float4*)W1,
                               (const float4*)W2, (const float4*)W3,
                               (float4*)p_xc, (float4*)p_w1,
                               (float4*)p_w2, (float4*)p_w3);          // 1
    k_zero<<<1, 32>>>();                                               // 2
    k_gate<<<T_TOK / 8, 256>>>(x, Wg);                                 // 3

    dim3 g1(E_NUM * (CAP / BM), H_DIM / BN);   // (256, 22)
    k_ffn1<<<g1, 256, SMEM1_BYTES>>>();                                // 4 <- profile target
    dim3 g2(E_NUM * (CAP / BM), D_DIM / BN);   // (256, 8)
    k_ffn2<<<g2, 256, SMEM2_BYTES>>>();                                // 5 <- profile target

    k_combine<<<(T_TOK * D_DIM / 4) / 256, 256>>>(out);                // 6
}